// round 15
// baseline (speedup 1.0000x reference)
#include <cuda_runtime.h>
#include <cuda_bf16.h>

#define D 384
#define N_ETYPES 8
#define THREADS 256
#define WARPS_PER_BLOCK (THREADS / 32)
#define EDGES_PER_WARP 16
#define FULL 0xffffffffu

__global__ __launch_bounds__(THREADS, 4) void distmult_kernel(
    const float* __restrict__ h,
    const int* __restrict__ u,
    const int* __restrict__ v,
    const int* __restrict__ etype,
    const float* __restrict__ rel_weight,
    float* __restrict__ out,
    int n_edges)
{
    __shared__ float s_rel[N_ETYPES * D];  // 12 KB
    for (int i = threadIdx.x; i < N_ETYPES * D; i += THREADS)
        s_rel[i] = rel_weight[i];
    __syncthreads();

    int gwarp = (blockIdx.x * THREADS + threadIdx.x) >> 5;
    int lane  = threadIdx.x & 31;

    int base = gwarp * EDGES_PER_WARP;
    if (base >= n_edges) return;
    int n_here = min(EDGES_PER_WARP, n_edges - base);

    // Coalesced batch load of this warp's edges' indices (lane i -> edge base+i).
    int ue = 0, ve = 0, ee = 0;
    if (lane < n_here) {
        ue = u[base + lane];
        ve = v[base + lane];
        ee = etype[base + lane];
    }

    int g  = lane >> 3;   // group 0..3: which of 4 concurrent edges
    int gl = lane & 7;    // lane within group

    float my_out = 0.0f;

    int n_pass = (n_here + 3) >> 2;          // up to 4 passes of 4 edges
    for (int k = 0; k < n_pass; k++) {
        // This group's edge for this pass (clamped for tail; result discarded).
        int eidx = min(4 * k + g, n_here - 1);
        int u0 = __shfl_sync(FULL, ue, eidx);
        int v0 = __shfl_sync(FULL, ve, eidx);
        int e0 = __shfl_sync(FULL, ee, eidx);

        const float4* __restrict__ hu = (const float4*)(h + (size_t)u0 * D);
        const float4* __restrict__ hv = (const float4*)(h + (size_t)v0 * D);
        const float4* __restrict__ rr = (const float4*)(s_rel + e0 * D);

        float acc = 0.0f;
#pragma unroll
        for (int c3 = 0; c3 < 3; c3++) {        // 3 chunks x 4 float4 per row
            float4 a[4], b[4];
            // Batch phase: 8 independent LDG.128 in flight before any use.
#pragma unroll
            for (int j = 0; j < 4; j++) {
                int idx = gl + (c3 * 4 + j) * 8;
                a[j] = __ldcg(hu + idx);        // bypass L1 (no reuse), keep L2
                b[j] = __ldcg(hv + idx);
            }
            // Consume phase.
#pragma unroll
            for (int j = 0; j < 4; j++) {
                int idx = gl + (c3 * 4 + j) * 8;
                float4 c = rr[idx];
                acc = fmaf(a[j].x * c.x, b[j].x, acc);
                acc = fmaf(a[j].y * c.y, b[j].y, acc);
                acc = fmaf(a[j].z * c.z, b[j].z, acc);
                acc = fmaf(a[j].w * c.w, b[j].w, acc);
            }
        }

        // Reduce within the 8-lane group (4 independent butterflies overlap).
        acc += __shfl_xor_sync(FULL, acc, 4);
        acc += __shfl_xor_sync(FULL, acc, 2);
        acc += __shfl_xor_sync(FULL, acc, 1);

        // Group g's total now replicated in lanes 8g..8g+7.
        // Owner lane (4k+g) fetches its result: src lane = 8*(lane - 4k).
        int src = (8 * (lane - 4 * k)) & 31;
        float r = __shfl_sync(FULL, acc, src);
        if ((lane >> 2) == k)
            my_out = 1.0f / (1.0f + __expf(-r));
    }

    // Coalesced store: lane i holds edge base+i's score.
    if (lane < n_here)
        out[base + lane] = my_out;
}

extern "C" void kernel_launch(void* const* d_in, const int* in_sizes, int n_in,
                              void* d_out, int out_size)
{
    const float* h   = (const float*)d_in[0];
    const int*   u   = (const int*)d_in[1];
    const int*   v   = (const int*)d_in[2];
    const int*   et  = (const int*)d_in[3];
    const float* rw  = (const float*)d_in[4];
    float*       out = (float*)d_out;

    int n_edges = in_sizes[1];

    int warps  = (n_edges + EDGES_PER_WARP - 1) / EDGES_PER_WARP;
    int blocks = (warps + WARPS_PER_BLOCK - 1) / WARPS_PER_BLOCK;
    distmult_kernel<<<blocks, THREADS>>>(h, u, v, et, rw, out, n_edges);
}